// round 1
// baseline (speedup 1.0000x reference)
#include <cuda_runtime.h>
#include <math.h>

#define IMG    64
#define NSLICE 16
#define NCOIL  4
#define NSING  4
#define NECHO  3
#define NRO    32
#define NPT    96
#define NEC    (NECHO * NCOIL)   // 12
#define NPIX   (IMG * IMG)       // 4096

// Scratch: Ur-folded, slice-gathered, coil-weighted images, one 64x64 complex
// image per (readout r, echo e, coil c).  32*12*4096 float2 = 12.6 MB.
__device__ float2 g_imgW[NRO * NEC * NPIX];

// ---------------------------------------------------------------------------
// Kernel 1: build imgW[r, e, c, y, x]
//   = sum_n Ur[r,n] * sum_z sign(z) * sing_c[x,y,z,n,e] * smap_c[c,x,y,z]
//                     * exp(-2*pi*i * kz_r * z / 16)
// One thread per (r, pixel).  grid = (16, 32), block = 256.
// ---------------------------------------------------------------------------
__global__ __launch_bounds__(256)
void prep_kernel(const float* __restrict__ singulars,   // [64,64,16,4,3,2]
                 const float* __restrict__ smap,        // [4,64,64,16,2]
                 const float* __restrict__ ur_list,     // [1,32,4]
                 const int*   __restrict__ sbin)        // [32]
{
    const int r   = blockIdx.y;
    const int pix = blockIdx.x * blockDim.x + threadIdx.x;  // 0..4095
    const int x   = pix & (IMG - 1);
    const int y   = pix >> 6;

    const int kz = sbin[r];

    // twiddle table (sign-folded) for this readout's kz
    __shared__ float2 wtab[NSLICE];
    if (threadIdx.x < NSLICE) {
        int z = threadIdx.x;
        float ang = -(2.0f * (float)M_PI / (float)NSLICE) * (float)(kz * z);
        float s, c;
        sincosf(ang, &s, &c);
        float sgn = (z & 1) ? -1.0f : 1.0f;
        wtab[z] = make_float2(c * sgn, s * sgn);
    }
    __syncthreads();

    float u[NSING];
#pragma unroll
    for (int n = 0; n < NSING; ++n) u[n] = ur_list[r * NSING + n];

    float accr[NECHO][NCOIL];
    float acci[NECHO][NCOIL];
#pragma unroll
    for (int e = 0; e < NECHO; ++e)
#pragma unroll
        for (int c = 0; c < NCOIL; ++c) { accr[e][c] = 0.0f; acci[e][c] = 0.0f; }

    // singulars base for (x,y): 16 z-chunks of 24 floats (6 float4 each)
    const float4* sg =
        (const float4*)(singulars + (size_t)(x * IMG + y) * NSLICE * (NSING * NECHO * 2));

    for (int z = 0; z < NSLICE; ++z) {
        float sv[24];
#pragma unroll
        for (int q = 0; q < 6; ++q) {
            float4 f = sg[z * 6 + q];
            sv[4 * q + 0] = f.x; sv[4 * q + 1] = f.y;
            sv[4 * q + 2] = f.z; sv[4 * q + 3] = f.w;
        }

        // coil sensitivities at (x,y,z)
        float2 sm[NCOIL];
#pragma unroll
        for (int c = 0; c < NCOIL; ++c) {
            sm[c] = *(const float2*)(smap +
                     ((size_t)(c * NPIX + x * IMG + y) * NSLICE + z) * 2);
        }

        const float2 w = wtab[z];

#pragma unroll
        for (int e = 0; e < NECHO; ++e) {
            float tr = 0.0f, ti = 0.0f;
#pragma unroll
            for (int n = 0; n < NSING; ++n) {
                tr = fmaf(u[n], sv[(n * NECHO + e) * 2 + 0], tr);
                ti = fmaf(u[n], sv[(n * NECHO + e) * 2 + 1], ti);
            }
            // (tr + i ti) * w
            float twr = tr * w.x - ti * w.y;
            float twi = tr * w.y + ti * w.x;
#pragma unroll
            for (int c = 0; c < NCOIL; ++c) {
                accr[e][c] = fmaf(twr, sm[c].x, accr[e][c]);
                accr[e][c] = fmaf(-twi, sm[c].y, accr[e][c]);
                acci[e][c] = fmaf(twr, sm[c].y, acci[e][c]);
                acci[e][c] = fmaf(twi, sm[c].x, acci[e][c]);
            }
        }
    }

#pragma unroll
    for (int e = 0; e < NECHO; ++e)
#pragma unroll
        for (int c = 0; c < NCOIL; ++c) {
            g_imgW[(size_t)(r * NEC + e * NCOIL + c) * NPIX + pix] =
                make_float2(accr[e][c], acci[e][c]);
        }
}

// ---------------------------------------------------------------------------
// Kernel 2: exact type-2 NUFFT per (r, e, c) image, one thread per point p.
//   out[p,c,r,e] = sum_{x,y} imgW[r,e,c,y,x] * exp(-i(w0*(x-32) + w1*(y-32)))
// Phase generated by complex-rotation recurrence (no per-pixel sincos).
// grid = (32, 12), block = 96 (one thread per point).
// ---------------------------------------------------------------------------
__global__ __launch_bounds__(96)
void nufft_kernel(const float* __restrict__ ktraj,   // [1,32,96,2]
                  float2* __restrict__ out)          // [96,4,32,3] complex
{
    const int r  = blockIdx.x;
    const int ec = blockIdx.y;

    __shared__ float2 sImg[NPIX];
    const float2* g = g_imgW + (size_t)(r * NEC + ec) * NPIX;
    for (int i = threadIdx.x; i < NPIX; i += blockDim.x) sImg[i] = g[i];
    __syncthreads();

    const int p = threadIdx.x;
    if (p >= NPT) return;

    const float w0 = ktraj[(r * NPT + p) * 2 + 0];
    const float w1 = ktraj[(r * NPT + p) * 2 + 1];

    // per-step rotations: exp(-i*w0), exp(-i*w1)
    float sx, cx;  sincosf(w0, &sx, &cx);
    float sy, cy_; sincosf(w1, &sy, &cy_);
    // starting phase at (x=0, y=0): exp(+i*32*(w0+w1))
    float rpr, rpi;
    sincosf(32.0f * (w0 + w1), &rpi, &rpr);

    float accr = 0.0f, acci = 0.0f;

    for (int yy = 0; yy < IMG; ++yy) {
        float pr = rpr, pi = rpi;
#pragma unroll 16
        for (int xx = 0; xx < IMG; ++xx) {
            float2 v = sImg[yy * IMG + xx];    // broadcast across the warp
            accr = fmaf(v.x,  pr, accr);
            accr = fmaf(-v.y, pi, accr);
            acci = fmaf(v.x,  pi, acci);
            acci = fmaf(v.y,  pr, acci);
            // phase *= exp(-i*w0) = (cx, -sx)
            float t = pr;
            pr = fmaf(pr, cx, pi * sx);
            pi = fmaf(pi, cx, -(t * sx));
        }
        // row phase *= exp(-i*w1) = (cy_, -sy)
        float t = rpr;
        rpr = fmaf(rpr, cy_, rpi * sy);
        rpi = fmaf(rpi, cy_, -(t * sy));
    }

    const int e = ec >> 2;       // ec = e*4 + c
    const int c = ec & 3;
    // out layout: [p, c, r, e] complex (stack real/imag last)
    out[((p * NCOIL + c) * NRO + r) * NECHO + e] = make_float2(accr, acci);
}

// ---------------------------------------------------------------------------
extern "C" void kernel_launch(void* const* d_in, const int* in_sizes, int n_in,
                              void* d_out, int out_size)
{
    const float* singulars = (const float*)d_in[0];
    const float* smap      = (const float*)d_in[1];
    const float* ktraj     = (const float*)d_in[2];
    const float* ur_list   = (const float*)d_in[3];
    const int*   sbin      = (const int*)d_in[4];
    // d_in[5] = dc (unused by the forward reference)

    float2* out = (float2*)d_out;

    prep_kernel<<<dim3(NPIX / 256, NRO), 256>>>(singulars, smap, ur_list, sbin);
    nufft_kernel<<<dim3(NRO, NEC), NPT>>>(ktraj, out);
}

// round 2
// speedup vs baseline: 2.1975x; 2.1975x over previous
#include <cuda_runtime.h>
#include <math.h>

#define IMG    64
#define NSLICE 16
#define NCOIL  4
#define NSING  4
#define NECHO  3
#define NRO    32
#define NPT    96
#define NEC    (NECHO * NCOIL)   // 12
#define NPIX   (IMG * IMG)       // 4096

// scf[kz][c][j=n*3+e][pix]  (25 MB)
__device__ float2 g_scf[NSLICE * NCOIL * (NSING * NECHO) * NPIX];
// imgW[r][ec=e*4+c][pix]    (12.6 MB)
__device__ float2 g_imgW[NRO * NEC * NPIX];
// phase tables [r][x][p], [r][y][p]  (1.5 MB each)
__device__ float2 g_ex[NRO * IMG * NPT];
__device__ float2 g_ey[NRO * IMG * NPT];

// ---------------------------------------------------------------------------
// Stage A: z-DFT (all 16 kz) of sign(z)*singulars*smap, per (pix, c, n).
// grid (16 pixblocks, 16 = c*4+n), block 256.
// ---------------------------------------------------------------------------
__global__ __launch_bounds__(256, 2)
void stageA_kernel(const float* __restrict__ singulars,   // [64,64,16,4,3,2]
                   const float* __restrict__ smap)        // [4,64,64,16,2]
{
    const int pix = blockIdx.x * 256 + threadIdx.x;
    const int cn  = blockIdx.y;
    const int c   = cn >> 2;
    const int n   = cn & 3;
    const int x   = pix & (IMG - 1);
    const int y   = pix >> 6;

    // DFT twiddles with sign(z) folded in: W[kz][z] = sign(z)*exp(-2pi*i*kz*z/16)
    __shared__ float2 W[NSLICE][NSLICE];
    {
        int kz = threadIdx.x >> 4, z = threadIdx.x & 15;
        float ang = -(2.0f * (float)M_PI / (float)NSLICE) * (float)(kz * z);
        float s, co; sincosf(ang, &s, &co);
        float sgn = (z & 1) ? -1.0f : 1.0f;
        W[kz][z] = make_float2(co * sgn, s * sgn);
    }
    __syncthreads();

    const float* vbase = singulars + ((size_t)(x * IMG + y) * NSLICE) * (NSING * NECHO * 2) + n * 6;
    const float* sbase = smap + ((size_t)(c * NPIX + x * IMG + y) * NSLICE) * 2;

    float accr[NSLICE][NECHO];
    float acci[NSLICE][NECHO];
#pragma unroll
    for (int kz = 0; kz < NSLICE; ++kz)
#pragma unroll
        for (int e = 0; e < NECHO; ++e) { accr[kz][e] = 0.f; acci[kz][e] = 0.f; }

    for (int z = 0; z < NSLICE; ++z) {
        float2 sm = *(const float2*)(sbase + z * 2);
        const float* v = vbase + z * (NSING * NECHO * 2);
        float2 v0 = *(const float2*)(v + 0);
        float2 v1 = *(const float2*)(v + 2);
        float2 v2 = *(const float2*)(v + 4);

        float tr[3], ti[3];
        tr[0] = v0.x * sm.x - v0.y * sm.y;  ti[0] = v0.x * sm.y + v0.y * sm.x;
        tr[1] = v1.x * sm.x - v1.y * sm.y;  ti[1] = v1.x * sm.y + v1.y * sm.x;
        tr[2] = v2.x * sm.x - v2.y * sm.y;  ti[2] = v2.x * sm.y + v2.y * sm.x;

#pragma unroll
        for (int kz = 0; kz < NSLICE; ++kz) {
            float2 w = W[kz][z];
#pragma unroll
            for (int e = 0; e < NECHO; ++e) {
                accr[kz][e] = fmaf(tr[e], w.x, accr[kz][e]);
                accr[kz][e] = fmaf(-ti[e], w.y, accr[kz][e]);
                acci[kz][e] = fmaf(tr[e], w.y, acci[kz][e]);
                acci[kz][e] = fmaf(ti[e], w.x, acci[kz][e]);
            }
        }
    }

#pragma unroll
    for (int kz = 0; kz < NSLICE; ++kz)
#pragma unroll
        for (int e = 0; e < NECHO; ++e) {
            g_scf[((size_t)(kz * NCOIL + c) * (NSING * NECHO) + n * NECHO + e) * NPIX + pix]
                = make_float2(accr[kz][e], acci[kz][e]);
        }
}

// ---------------------------------------------------------------------------
// Stage B: mix with Ur, gather slice bin: imgW[r][e*4+c][pix]
// grid (16 pixblocks, 32 r), block 256.
// ---------------------------------------------------------------------------
__global__ __launch_bounds__(256)
void stageB_kernel(const float* __restrict__ ur_list,   // [1,32,4]
                   const int*   __restrict__ sbin)      // [32]
{
    const int pix = blockIdx.x * 256 + threadIdx.x;
    const int r   = blockIdx.y;
    const int kzr = sbin[r];

    float u[NSING];
#pragma unroll
    for (int n = 0; n < NSING; ++n) u[n] = ur_list[r * NSING + n];

    const float2* base = g_scf + (size_t)(kzr * NCOIL) * (NSING * NECHO) * NPIX;

#pragma unroll
    for (int e = 0; e < NECHO; ++e) {
#pragma unroll
        for (int c = 0; c < NCOIL; ++c) {
            float ar = 0.f, ai = 0.f;
#pragma unroll
            for (int n = 0; n < NSING; ++n) {
                float2 s = base[((size_t)c * (NSING * NECHO) + n * NECHO + e) * NPIX + pix];
                ar = fmaf(u[n], s.x, ar);
                ai = fmaf(u[n], s.y, ai);
            }
            g_imgW[((size_t)r * NEC + e * NCOIL + c) * NPIX + pix] = make_float2(ar, ai);
        }
    }
}

// ---------------------------------------------------------------------------
// Phase tables: g_ex[r][x][p] = exp(-i*w0*(x-32)), g_ey[r][y][p] = exp(-i*w1*(y-32))
// grid 32 (r), block 96 (p).
// ---------------------------------------------------------------------------
__global__ __launch_bounds__(96)
void exgen_kernel(const float* __restrict__ ktraj)   // [1,32,96,2]
{
    const int r = blockIdx.x;
    const int p = threadIdx.x;
    const float w0 = ktraj[(r * NPT + p) * 2 + 0];
    const float w1 = ktraj[(r * NPT + p) * 2 + 1];

    // ex
    {
        float sx, cx; sincosf(w0, &sx, &cx);      // step = (cx, -sx)
        float pr, pi; sincosf(32.0f * w0, &pi, &pr); // start = exp(+i*32*w0)
        for (int x = 0; x < IMG; ++x) {
            g_ex[(r * IMG + x) * NPT + p] = make_float2(pr, pi);
            float t = pr;
            pr = fmaf(pr, cx, pi * sx);
            pi = fmaf(pi, cx, -(t * sx));
        }
    }
    // ey
    {
        float sy, cy; sincosf(w1, &sy, &cy);
        float pr, pi; sincosf(32.0f * w1, &pi, &pr);
        for (int y = 0; y < IMG; ++y) {
            g_ey[(r * IMG + y) * NPT + p] = make_float2(pr, pi);
            float t = pr;
            pr = fmaf(pr, cy, pi * sy);
            pi = fmaf(pi, cy, -(t * sy));
        }
    }
}

// ---------------------------------------------------------------------------
// NUFFT: register-tiled complex GEMM t1[p,y] = sum_x img[y,x]*ex[x,p],
// then out[p] = sum_y t1[p,y]*ey[y,p].  grid (32 r, 12 ec), block 384.
// Thread tile: 4p x 4y.  tx in [0,24), ty in [0,16).
// ---------------------------------------------------------------------------
#define TSTRIDE 66   // padded row stride (float2) for transposed image

__global__ __launch_bounds__(384)
void nufft_kernel(float2* __restrict__ out)   // [96,4,32,3] complex
{
    extern __shared__ float2 sh[];
    float2* sT  = sh;                  // [64][TSTRIDE] transposed image: sT[x][y]
    float2* sEx = sh + IMG * TSTRIDE;  // [64][96]: sEx[x][p]

    const int r  = blockIdx.x;
    const int ec = blockIdx.y;
    const int tid = threadIdx.x;

    // load + transpose image
    const float2* g = g_imgW + (size_t)(r * NEC + ec) * NPIX;
    for (int i = tid; i < NPIX; i += 384) {
        float2 v = g[i];
        int x = i & (IMG - 1), y = i >> 6;
        sT[x * TSTRIDE + y] = v;
    }
    // load ex slab
    const float2* gex = g_ex + (size_t)r * IMG * NPT;
    for (int i = tid; i < IMG * NPT; i += 384) sEx[i] = gex[i];
    __syncthreads();

    const int tx = tid % 24;       // p-tile
    const int ty = tid / 24;       // y-tile
    const int p0 = tx * 4;
    const int y0 = ty * 4;

    float ar[4][4], ai[4][4];      // [pp][yy]
#pragma unroll
    for (int a = 0; a < 4; ++a)
#pragma unroll
        for (int b = 0; b < 4; ++b) { ar[a][b] = 0.f; ai[a][b] = 0.f; }

#pragma unroll 4
    for (int x = 0; x < IMG; ++x) {
        const float4* pe = reinterpret_cast<const float4*>(&sEx[x * NPT + p0]);
        float4 e01 = pe[0], e23 = pe[1];
        const float4* pi4 = reinterpret_cast<const float4*>(&sT[x * TSTRIDE + y0]);
        float4 i01 = pi4[0], i23 = pi4[1];

        float2 ev[4] = { make_float2(e01.x, e01.y), make_float2(e01.z, e01.w),
                         make_float2(e23.x, e23.y), make_float2(e23.z, e23.w) };
        float2 iv[4] = { make_float2(i01.x, i01.y), make_float2(i01.z, i01.w),
                         make_float2(i23.x, i23.y), make_float2(i23.z, i23.w) };

#pragma unroll
        for (int pp = 0; pp < 4; ++pp)
#pragma unroll
            for (int yy = 0; yy < 4; ++yy) {
                ar[pp][yy] = fmaf(ev[pp].x,  iv[yy].x, ar[pp][yy]);
                ar[pp][yy] = fmaf(-ev[pp].y, iv[yy].y, ar[pp][yy]);
                ai[pp][yy] = fmaf(ev[pp].x,  iv[yy].y, ai[pp][yy]);
                ai[pp][yy] = fmaf(ev[pp].y,  iv[yy].x, ai[pp][yy]);
            }
    }

    __syncthreads();               // done with sEx; reuse as reduction buffer
    float2* sRed = sEx;            // [96][16]

    const float2* gey = g_ey + (size_t)r * IMG * NPT;
#pragma unroll
    for (int pp = 0; pp < 4; ++pp) {
        float outr = 0.f, outi = 0.f;
#pragma unroll
        for (int yy = 0; yy < 4; ++yy) {
            float2 ey = gey[(y0 + yy) * NPT + p0 + pp];
            outr = fmaf(ar[pp][yy], ey.x, outr);
            outr = fmaf(-ai[pp][yy], ey.y, outr);
            outi = fmaf(ar[pp][yy], ey.y, outi);
            outi = fmaf(ai[pp][yy], ey.x, outi);
        }
        sRed[(p0 + pp) * 16 + ty] = make_float2(outr, outi);
    }
    __syncthreads();

    if (tid < NPT) {
        float sr = 0.f, si = 0.f;
#pragma unroll
        for (int k = 0; k < 16; ++k) {
            float2 v = sRed[tid * 16 + k];
            sr += v.x; si += v.y;
        }
        const int e = ec >> 2;
        const int c = ec & 3;
        out[((tid * NCOIL + c) * NRO + r) * NECHO + e] = make_float2(sr, si);
    }
}

// ---------------------------------------------------------------------------
extern "C" void kernel_launch(void* const* d_in, const int* in_sizes, int n_in,
                              void* d_out, int out_size)
{
    const float* singulars = (const float*)d_in[0];
    const float* smap      = (const float*)d_in[1];
    const float* ktraj     = (const float*)d_in[2];
    const float* ur_list   = (const float*)d_in[3];
    const int*   sbin      = (const int*)d_in[4];
    // d_in[5] = dc (unused by the forward reference)

    float2* out = (float2*)d_out;

    const int smemNufft = (IMG * TSTRIDE + IMG * NPT) * (int)sizeof(float2); // ~81KB
    cudaFuncSetAttribute(nufft_kernel, cudaFuncAttributeMaxDynamicSharedMemorySize, smemNufft);

    stageA_kernel<<<dim3(NPIX / 256, 16), 256>>>(singulars, smap);
    stageB_kernel<<<dim3(NPIX / 256, NRO), 256>>>(ur_list, sbin);
    exgen_kernel<<<NRO, NPT>>>(ktraj);
    nufft_kernel<<<dim3(NRO, NEC), 384, smemNufft>>>(out);
}